// round 6
// baseline (speedup 1.0000x reference)
#include <cuda_runtime.h>
#include <math_constants.h>

// PCEN: [B=32, T=4096, F=256] fp32.
//   ema_t = w*x_t + (1-w)*ema_{t-1},  ema_{-1} = x_0
//   v     = (x*(EPS+ema)^(-g) + bias)^(1/r) - bias^(1/r)
//   out   = 2*(v - min v)/(max v - min v) - 1   (global min/max)
//
// Round 5: R3 structure (kernel boundary = global sync, no lookback) but:
//  - B processed in two halves; K3(half)'s re-read of x hits L2 (67MB < 126MB)
//    because only the tiny K2 runs between K1(half) and K3(half).
//  - K4(h1) runs right after K3(h1) so h1 is L2-hot for the output pass too.
//  - float4 vectorization: 4 f-chains per thread (512B/warp accesses, 4-way ILP).
//  - sqrt fast path for root==2 in K4.

#define EPSC 1e-6f
#define BB   32
#define TT   4096
#define FF   256
#define F4   (FF / 4)               // 64 float4 lanes
#define LL   128
#define NCHUNK (TT / LL)            // 32
#define HALF_B (BB / 2)             // 16
#define NT_H   (HALF_B * NCHUNK * F4)  // 32768 threads per half (K1/K3/K4)
#define CH4_H  (HALF_B * F4)           // 1024 f4-chains per half (K2)

__device__ float4   g_S4[BB * NCHUNK * F4];  // chunk aggregates
__device__ float4   g_A4[BB * NCHUNK * F4];  // chunk carry-ins
__device__ unsigned g_minmax[2];             // ordered-uint min/max keys of u

__device__ __forceinline__ unsigned f2key(float f) {
    unsigned u = __float_as_uint(f);
    return (u & 0x80000000u) ? ~u : (u | 0x80000000u);
}
__device__ __forceinline__ float key2f(unsigned k) {
    return __uint_as_float((k & 0x80000000u) ? (k & 0x7FFFFFFFu) : ~k);
}

// ---------------------------------------------------------------------------
// K1: per-chunk local scan (zero carry) -> g_S4. One half of B.
// tid: f4 = tid&63, c = (tid>>6)&31, bh = tid>>11.
// ---------------------------------------------------------------------------
__global__ void __launch_bounds__(128) k1_chunk_scan(
    const float* __restrict__ xf, const float* __restrict__ smooth, int b0)
{
    int tid = blockIdx.x * blockDim.x + threadIdx.x;
    int f4 = tid & (F4 - 1);
    int c  = (tid >> 6) & (NCHUNK - 1);
    int b  = b0 + (tid >> 11);

    float w   = fminf(fmaxf(smooth[0], 0.0f), 1.0f);
    float omw = 1.0f - w;

    const float4* p = (const float4*)xf + ((size_t)(b * TT + c * LL)) * F4 + f4;

    float4 a = make_float4(0.f, 0.f, 0.f, 0.f);
    #pragma unroll 8
    for (int i = 0; i < LL; i++) {
        float4 xv = p[(size_t)i * F4];
        a.x = fmaf(omw, a.x, w * xv.x);
        a.y = fmaf(omw, a.y, w * xv.y);
        a.z = fmaf(omw, a.z, w * xv.z);
        a.w = fmaf(omw, a.w, w * xv.w);
    }
    g_S4[(b * NCHUNK + c) * F4 + f4] = a;
}

// ---------------------------------------------------------------------------
// K2: per-chain sequential combine of 32 chunk carries -> g_A4. One half.
// First half (b0==0) also resets g_minmax (replay-safe, ordered by stream).
// ---------------------------------------------------------------------------
__global__ void __launch_bounds__(128) k2_combine(
    const float* __restrict__ xf, const float* __restrict__ smooth, int b0)
{
    int tid = blockIdx.x * blockDim.x + threadIdx.x;
    if (b0 == 0 && tid == 0) {
        g_minmax[0] = 0xFFFFFFFFu;  // min key (= +inf)
        g_minmax[1] = 0x00000000u;  // max key (= -inf)
    }
    if (tid >= CH4_H) return;

    int f4 = tid & (F4 - 1);
    int b  = b0 + (tid >> 6);

    float w   = fminf(fmaxf(smooth[0], 0.0f), 1.0f);
    float omw = 1.0f - w;
    float D = omw;                  // omw^128 via 7 squarings
    #pragma unroll
    for (int i = 0; i < 7; i++) D *= D;

    float4 A = ((const float4*)xf)[(size_t)b * TT * F4 + f4];  // x[b,0,f4..]
    int base = (b * NCHUNK) * F4 + f4;
    #pragma unroll
    for (int c = 0; c < NCHUNK; c++) {
        g_A4[base + c * F4] = A;
        float4 S = g_S4[base + c * F4];
        A.x = fmaf(D, A.x, S.x);
        A.y = fmaf(D, A.y, S.y);
        A.z = fmaf(D, A.z, S.z);
        A.w = fmaf(D, A.w, S.w);
    }
}

// ---------------------------------------------------------------------------
// K3: rescan (L2-hot) with carry, reduce global min/max of
// u = x*(EPS+ema)^(-g). v is monotone in u, so this suffices.
// ---------------------------------------------------------------------------
__global__ void __launch_bounds__(128) k3_minmax(
    const float* __restrict__ xf,
    const float* __restrict__ gain, const float* __restrict__ smooth, int b0)
{
    int tid = blockIdx.x * blockDim.x + threadIdx.x;
    int f4 = tid & (F4 - 1);
    int c  = (tid >> 6) & (NCHUNK - 1);
    int b  = b0 + (tid >> 11);

    float w   = fminf(fmaxf(smooth[0], 0.0f), 1.0f);
    float omw = 1.0f - w;
    float g   = fminf(gain[0], 1.0f);

    const float4* p = (const float4*)xf + ((size_t)(b * TT + c * LL)) * F4 + f4;

    float4 a = g_A4[(b * NCHUNK + c) * F4 + f4];
    float mn = CUDART_INF_F, mx = -CUDART_INF_F;

    #pragma unroll 4
    for (int i = 0; i < LL; i++) {
        float4 xv = p[(size_t)i * F4];
        a.x = fmaf(omw, a.x, w * xv.x);
        a.y = fmaf(omw, a.y, w * xv.y);
        a.z = fmaf(omw, a.z, w * xv.z);
        a.w = fmaf(omw, a.w, w * xv.w);
        float u0 = xv.x * __powf(EPSC + a.x, -g);
        float u1 = xv.y * __powf(EPSC + a.y, -g);
        float u2 = xv.z * __powf(EPSC + a.z, -g);
        float u3 = xv.w * __powf(EPSC + a.w, -g);
        mn = fminf(mn, fminf(fminf(u0, u1), fminf(u2, u3)));
        mx = fmaxf(mx, fmaxf(fmaxf(u0, u1), fmaxf(u2, u3)));
    }

    #pragma unroll
    for (int o = 16; o; o >>= 1) {
        mn = fminf(mn, __shfl_xor_sync(0xFFFFFFFFu, mn, o));
        mx = fmaxf(mx, __shfl_xor_sync(0xFFFFFFFFu, mx, o));
    }
    __shared__ float smn[4], smx[4];
    int wid = threadIdx.x >> 5, lane = threadIdx.x & 31;
    if (lane == 0) { smn[wid] = mn; smx[wid] = mx; }
    __syncthreads();
    if (threadIdx.x == 0) {
        float bmn = fminf(fminf(smn[0], smn[1]), fminf(smn[2], smn[3]));
        float bmx = fmaxf(fmaxf(smx[0], smx[1]), fmaxf(smx[2], smx[3]));
        atomicMin(&g_minmax[0], f2key(bmn));
        atomicMax(&g_minmax[1], f2key(bmx));
    }
}

// ---------------------------------------------------------------------------
// K4: rescan, v' = (u+bias)^(1/r), normalize, write.  bias^(1/r) cancels.
// vmn/vmx use the SAME formula as the loop body (incl. sqrt fast path),
// so extreme elements map exactly to -1/+1.
// ---------------------------------------------------------------------------
__global__ void __launch_bounds__(128) k4_output(
    const float* __restrict__ xf, float* __restrict__ outf,
    const float* __restrict__ gain, const float* __restrict__ bias,
    const float* __restrict__ root, const float* __restrict__ smooth, int b0)
{
    int tid = blockIdx.x * blockDim.x + threadIdx.x;
    int f4 = tid & (F4 - 1);
    int c  = (tid >> 6) & (NCHUNK - 1);
    int b  = b0 + (tid >> 11);

    float w   = fminf(fmaxf(smooth[0], 0.0f), 1.0f);
    float omw = 1.0f - w;
    float g   = fminf(gain[0], 1.0f);
    float r   = fmaxf(root[0], 1.0f);
    float oor = 1.0f / r;
    float bs  = bias[0];
    bool  sq  = (oor == 0.5f);      // root == 2 -> exact sqrt fast path

    float umn = key2f(g_minmax[0]);
    float umx = key2f(g_minmax[1]);
    float vmn = sq ? sqrtf(umn + bs) : __powf(umn + bs, oor);
    float vmx = sq ? sqrtf(umx + bs) : __powf(umx + bs, oor);
    float sc  = 2.0f / (vmx - vmn);

    size_t off = ((size_t)(b * TT + c * LL)) * F4 + f4;
    const float4* p = (const float4*)xf + off;
    float4*       q = (float4*)outf + off;

    float4 a = g_A4[(b * NCHUNK + c) * F4 + f4];

    #pragma unroll 4
    for (int i = 0; i < LL; i++) {
        float4 xv = p[(size_t)i * F4];
        a.x = fmaf(omw, a.x, w * xv.x);
        a.y = fmaf(omw, a.y, w * xv.y);
        a.z = fmaf(omw, a.z, w * xv.z);
        a.w = fmaf(omw, a.w, w * xv.w);
        float u0 = xv.x * __powf(EPSC + a.x, -g);
        float u1 = xv.y * __powf(EPSC + a.y, -g);
        float u2 = xv.z * __powf(EPSC + a.z, -g);
        float u3 = xv.w * __powf(EPSC + a.w, -g);
        float v0 = sq ? sqrtf(u0 + bs) : __powf(u0 + bs, oor);
        float v1 = sq ? sqrtf(u1 + bs) : __powf(u1 + bs, oor);
        float v2 = sq ? sqrtf(u2 + bs) : __powf(u2 + bs, oor);
        float v3 = sq ? sqrtf(u3 + bs) : __powf(u3 + bs, oor);
        float4 o;
        o.x = fmaf(v0 - vmn, sc, -1.0f);
        o.y = fmaf(v1 - vmn, sc, -1.0f);
        o.z = fmaf(v2 - vmn, sc, -1.0f);
        o.w = fmaf(v3 - vmn, sc, -1.0f);
        q[(size_t)i * F4] = o;
    }
}

extern "C" void kernel_launch(void* const* d_in, const int* in_sizes, int n_in,
                              void* d_out, int out_size)
{
    const float* x      = (const float*)d_in[0];
    const float* gain   = (const float*)d_in[1];
    const float* bias   = (const float*)d_in[2];
    const float* root   = (const float*)d_in[3];
    const float* smooth = (const float*)d_in[4];
    float* out = (float*)d_out;

    const int GK = NT_H / 128;      // 256 blocks per half for K1/K3/K4
    const int G2 = (CH4_H + 127) / 128;  // 8 blocks for K2

    // half 0: scan -> combine -> minmax (x[h0] L2-hot for K3)
    k1_chunk_scan<<<GK, 128>>>(x, smooth, 0);
    k2_combine  <<<G2, 128>>>(x, smooth, 0);
    k3_minmax   <<<GK, 128>>>(x, gain, smooth, 0);
    // half 1
    k1_chunk_scan<<<GK, 128>>>(x, smooth, HALF_B);
    k2_combine  <<<G2, 128>>>(x, smooth, HALF_B);
    k3_minmax   <<<GK, 128>>>(x, gain, smooth, HALF_B);
    // output: h1 first (still L2-hot), then h0
    k4_output   <<<GK, 128>>>(x, out, gain, bias, root, smooth, HALF_B);
    k4_output   <<<GK, 128>>>(x, out, gain, bias, root, smooth, 0);
}

// round 7
// speedup vs baseline: 1.2087x; 1.2087x over previous
#include <cuda_runtime.h>
#include <math_constants.h>

// PCEN: [B=32, T=4096, F=256] fp32.
//   ema_t = w*x_t + (1-w)*ema_{t-1},  ema_{-1} = x_0
//   v     = (x*(EPS+ema)^(-g) + bias)^(1/r) - bias^(1/r)
//   out   = 2*(v - min v)/(max v - min v) - 1   (global min/max)
//
// Round 6: R3's proven SCALAR layout (262144 threads, 256/block — the config
// that saturated HBM), split into two B-halves so K3's re-read and K4(h1)'s
// read hit L2 (67MB half < 126MB L2). R5's float4 regression was an occupancy
// collapse (10.5% occ), not a split failure — scalar threads restore it.

#define EPSC 1e-6f
#define BB   32
#define TT   4096
#define FF   256
#define LL   128
#define NCHUNK (TT / LL)            // 32
#define HALF_B (BB / 2)             // 16
#define NT_H   (HALF_B * NCHUNK * FF)  // 131072 threads per half
#define CH_H   (HALF_B * FF)           // 4096 chains per half (K2)

__device__ float    g_S[BB * NCHUNK * FF];  // chunk aggregates [(b,c,f)]
__device__ float    g_A[BB * NCHUNK * FF];  // chunk carry-ins  [(b,c,f)]
__device__ unsigned g_minmax[2];            // ordered-uint min/max keys of u

__device__ __forceinline__ unsigned f2key(float f) {
    unsigned u = __float_as_uint(f);
    return (u & 0x80000000u) ? ~u : (u | 0x80000000u);
}
__device__ __forceinline__ float key2f(unsigned k) {
    return __uint_as_float((k & 0x80000000u) ? (k & 0x7FFFFFFFu) : ~k);
}

// ---------------------------------------------------------------------------
// K1: per-chunk local scan with zero carry -> g_S. One B-half.
// tid: f = tid&255 (coalesced), c = (tid>>8)&31, b = b0 + (tid>>13).
// ---------------------------------------------------------------------------
__global__ void __launch_bounds__(256) k1_chunk_scan(
    const float* __restrict__ x, const float* __restrict__ smooth, int b0)
{
    int tid = blockIdx.x * blockDim.x + threadIdx.x;
    int f = tid & (FF - 1);
    int c = (tid >> 8) & (NCHUNK - 1);
    int b = b0 + (tid >> 13);

    float w   = fminf(fmaxf(smooth[0], 0.0f), 1.0f);
    float omw = 1.0f - w;

    const float* p = x + ((size_t)(b * TT + c * LL)) * FF + f;

    float a = 0.0f;
    #pragma unroll 8
    for (int i = 0; i < LL; i++) {
        a = fmaf(omw, a, w * p[(size_t)i * FF]);
    }
    g_S[(b * NCHUNK + c) * FF + f] = a;
}

// ---------------------------------------------------------------------------
// K2: per-chain sequential combine of 32 chunk carries -> g_A. One half.
// First half also resets g_minmax (stream-ordered, replay-safe).
// ---------------------------------------------------------------------------
__global__ void __launch_bounds__(256) k2_combine(
    const float* __restrict__ x, const float* __restrict__ smooth, int b0)
{
    int tid = blockIdx.x * blockDim.x + threadIdx.x;
    if (b0 == 0 && tid == 0) {
        g_minmax[0] = 0xFFFFFFFFu;  // min key (= +inf)
        g_minmax[1] = 0x00000000u;  // max key (= -inf)
    }
    if (tid >= CH_H) return;

    int f = tid & (FF - 1);
    int b = b0 + (tid >> 8);

    float w   = fminf(fmaxf(smooth[0], 0.0f), 1.0f);
    float omw = 1.0f - w;
    float D = omw;                  // omw^128 via 7 squarings
    #pragma unroll
    for (int i = 0; i < 7; i++) D *= D;

    float A = x[(size_t)b * TT * FF + f];   // ema_{-1} = x[b,0,f]
    int base = (b * NCHUNK) * FF + f;
    #pragma unroll
    for (int c = 0; c < NCHUNK; c++) {
        g_A[base + c * FF] = A;
        A = fmaf(D, A, g_S[base + c * FF]);
    }
}

// ---------------------------------------------------------------------------
// K3: rescan (L2-hot re-read) with true carry, reduce global min/max of
// u = x*(EPS+ema)^(-g). v is monotone in u so this suffices; 1 MUFU pair/elem.
// ---------------------------------------------------------------------------
__global__ void __launch_bounds__(256) k3_minmax(
    const float* __restrict__ x,
    const float* __restrict__ gain, const float* __restrict__ smooth, int b0)
{
    int tid = blockIdx.x * blockDim.x + threadIdx.x;
    int f = tid & (FF - 1);
    int c = (tid >> 8) & (NCHUNK - 1);
    int b = b0 + (tid >> 13);

    float w   = fminf(fmaxf(smooth[0], 0.0f), 1.0f);
    float omw = 1.0f - w;
    float g   = fminf(gain[0], 1.0f);

    const float* p = x + ((size_t)(b * TT + c * LL)) * FF + f;

    float a  = g_A[(b * NCHUNK + c) * FF + f];
    float mn = CUDART_INF_F, mx = -CUDART_INF_F;

    #pragma unroll 4
    for (int i = 0; i < LL; i++) {
        float xv = p[(size_t)i * FF];
        a = fmaf(omw, a, w * xv);
        float u = xv * __powf(EPSC + a, -g);
        mn = fminf(mn, u);
        mx = fmaxf(mx, u);
    }

    #pragma unroll
    for (int o = 16; o; o >>= 1) {
        mn = fminf(mn, __shfl_xor_sync(0xFFFFFFFFu, mn, o));
        mx = fmaxf(mx, __shfl_xor_sync(0xFFFFFFFFu, mx, o));
    }
    __shared__ float smn[8], smx[8];
    int wid = threadIdx.x >> 5, lane = threadIdx.x & 31;
    if (lane == 0) { smn[wid] = mn; smx[wid] = mx; }
    __syncthreads();
    if (threadIdx.x == 0) {
        float bmn = smn[0], bmx = smx[0];
        #pragma unroll
        for (int i = 1; i < 8; i++) {
            bmn = fminf(bmn, smn[i]);
            bmx = fmaxf(bmx, smx[i]);
        }
        atomicMin(&g_minmax[0], f2key(bmn));
        atomicMax(&g_minmax[1], f2key(bmx));
    }
}

// ---------------------------------------------------------------------------
// K4: rescan, v' = (u+bias)^(1/r), normalize, write. bias^(1/r) cancels.
// vmn/vmx use the SAME formula as the loop body (incl. sqrt fast path for
// root==2), so the extreme elements map exactly to -1/+1.
// ---------------------------------------------------------------------------
__global__ void __launch_bounds__(256) k4_output(
    const float* __restrict__ x, float* __restrict__ out,
    const float* __restrict__ gain, const float* __restrict__ bias,
    const float* __restrict__ root, const float* __restrict__ smooth, int b0)
{
    int tid = blockIdx.x * blockDim.x + threadIdx.x;
    int f = tid & (FF - 1);
    int c = (tid >> 8) & (NCHUNK - 1);
    int b = b0 + (tid >> 13);

    float w   = fminf(fmaxf(smooth[0], 0.0f), 1.0f);
    float omw = 1.0f - w;
    float g   = fminf(gain[0], 1.0f);
    float r   = fmaxf(root[0], 1.0f);
    float oor = 1.0f / r;
    float bs  = bias[0];
    bool  sq  = (oor == 0.5f);      // root == 2 -> exact sqrt fast path

    float umn = key2f(g_minmax[0]);
    float umx = key2f(g_minmax[1]);
    float vmn = sq ? sqrtf(umn + bs) : __powf(umn + bs, oor);
    float vmx = sq ? sqrtf(umx + bs) : __powf(umx + bs, oor);
    float sc  = 2.0f / (vmx - vmn);

    size_t off = ((size_t)(b * TT + c * LL)) * FF + f;
    const float* p = x + off;
    float*       q = out + off;

    float a = g_A[(b * NCHUNK + c) * FF + f];

    #pragma unroll 4
    for (int i = 0; i < LL; i++) {
        float xv = p[(size_t)i * FF];
        a = fmaf(omw, a, w * xv);
        float u  = xv * __powf(EPSC + a, -g);
        float vp = sq ? sqrtf(u + bs) : __powf(u + bs, oor);
        q[(size_t)i * FF] = fmaf(vp - vmn, sc, -1.0f);
    }
}

extern "C" void kernel_launch(void* const* d_in, const int* in_sizes, int n_in,
                              void* d_out, int out_size)
{
    const float* x      = (const float*)d_in[0];
    const float* gain   = (const float*)d_in[1];
    const float* bias   = (const float*)d_in[2];
    const float* root   = (const float*)d_in[3];
    const float* smooth = (const float*)d_in[4];
    float* out = (float*)d_out;

    const int GK = NT_H / 256;           // 512 blocks per half
    const int G2 = (CH_H + 255) / 256;   // 16 blocks for K2

    // half 0: scan -> combine -> minmax (x[h0] stays L2-hot across K2)
    k1_chunk_scan<<<GK, 256>>>(x, smooth, 0);
    k2_combine  <<<G2, 256>>>(x, smooth, 0);
    k3_minmax   <<<GK, 256>>>(x, gain, smooth, 0);
    // half 1
    k1_chunk_scan<<<GK, 256>>>(x, smooth, HALF_B);
    k2_combine  <<<G2, 256>>>(x, smooth, HALF_B);
    k3_minmax   <<<GK, 256>>>(x, gain, smooth, HALF_B);
    // output: h1 first (x[h1] still L2-hot), then h0
    k4_output   <<<GK, 256>>>(x, out, gain, bias, root, smooth, HALF_B);
    k4_output   <<<GK, 256>>>(x, out, gain, bias, root, smooth, 0);
}

// round 12
// speedup vs baseline: 1.8058x; 1.4940x over previous
#include <cuda_runtime.h>
#include <math_constants.h>

// PCEN: [B=32, T=4096, F=256] fp32.
//   ema_t = w*x_t + (1-w)*ema_{t-1},  ema_{-1} = x_0
//   v     = (x*(EPS+ema)^(-g) + bias)^(1/r) - bias^(1/r)
//   out   = 2*(v - min v)/(max v - min v) - 1   (global min/max)
//
// Round 11: PROVEN R3 structure (4 launches, full 262144-thread grids,
// L=128 chunks — measured 118.9us) + sqrt fast path for root==2 in the
// output pass (cuts K4's per-element MUFU/issue pressure, which ncu showed
// capping K4 at 56% DRAM) + deeper unroll for MLP.

#define EPSC 1e-6f
#define BB   32
#define TT   4096
#define FF   256
#define LL   128
#define NCHUNK (TT / LL)          // 32
#define NCHAIN (BB * FF)          // 8192
#define NTHREAD (NCHAIN * NCHUNK) // 262144

__device__ float    g_S[NTHREAD];   // chunk partial EMA sums, tid = (b,c,f)
__device__ float    g_A[NTHREAD];   // chunk carry-in values, same layout
__device__ unsigned g_minmax[2];    // [0]=min key of u, [1]=max key of u

// Monotone float <-> uint mapping (handles sign).
__device__ __forceinline__ unsigned f2key(float f) {
    unsigned u = __float_as_uint(f);
    return (u & 0x80000000u) ? ~u : (u | 0x80000000u);
}
__device__ __forceinline__ float key2f(unsigned k) {
    return __uint_as_float((k & 0x80000000u) ? (k & 0x7FFFFFFFu) : ~k);
}

// ---------------------------------------------------------------------------
// K1: per-chunk local scan with zero carry-in -> g_S.
// tid: f = tid&255 (coalesced), c = (tid>>8)&31, b = tid>>13.
// ---------------------------------------------------------------------------
__global__ void __launch_bounds__(256) k1_chunk_scan(
    const float* __restrict__ x, const float* __restrict__ smooth)
{
    int tid = blockIdx.x * blockDim.x + threadIdx.x;
    int f = tid & (FF - 1);
    int c = (tid >> 8) & (NCHUNK - 1);
    int b = tid >> 13;

    float w   = fminf(fmaxf(smooth[0], 0.0f), 1.0f);
    float omw = 1.0f - w;

    const float* p = x + ((size_t)(b * TT + c * LL)) * FF + f;

    float a = 0.0f;
    #pragma unroll 8
    for (int i = 0; i < LL; i++) {
        a = fmaf(omw, a, w * p[(size_t)i * FF]);
    }
    g_S[tid] = a;
}

// ---------------------------------------------------------------------------
// K2: per-chain sequential combine of 32 chunk carries -> g_A. Inits minmax.
// ---------------------------------------------------------------------------
__global__ void __launch_bounds__(256) k2_combine(
    const float* __restrict__ x, const float* __restrict__ smooth)
{
    int tid = blockIdx.x * blockDim.x + threadIdx.x;
    if (tid == 0) {
        g_minmax[0] = 0xFFFFFFFFu;  // min key init (= +inf)
        g_minmax[1] = 0x00000000u;  // max key init (= -inf)
    }
    if (tid >= NCHAIN) return;

    int b = tid >> 8;
    int f = tid & (FF - 1);

    float w   = fminf(fmaxf(smooth[0], 0.0f), 1.0f);
    float omw = 1.0f - w;
    float D = omw;                 // omw^128 via 7 squarings
    #pragma unroll
    for (int i = 0; i < 7; i++) D *= D;

    float A = x[(size_t)b * TT * FF + f];  // ema_{-1} = x[b,0,f]
    int base = (b * NCHUNK) * FF + f;
    #pragma unroll
    for (int c = 0; c < NCHUNK; c++) {
        g_A[base + c * FF] = A;
        A = fmaf(D, A, g_S[base + c * FF]);
    }
}

// ---------------------------------------------------------------------------
// K3: rescan with carry, reduce global min/max of u = x*(EPS+ema)^(-g).
// v is monotone in u (bias>0, 0<1/r<=1), so min/max over u suffices.
// ---------------------------------------------------------------------------
__global__ void __launch_bounds__(256) k3_minmax(
    const float* __restrict__ x,
    const float* __restrict__ gain, const float* __restrict__ smooth)
{
    int tid = blockIdx.x * blockDim.x + threadIdx.x;
    int f = tid & (FF - 1);
    int c = (tid >> 8) & (NCHUNK - 1);
    int b = tid >> 13;

    float w   = fminf(fmaxf(smooth[0], 0.0f), 1.0f);
    float omw = 1.0f - w;
    float g   = fminf(gain[0], 1.0f);

    const float* p = x + ((size_t)(b * TT + c * LL)) * FF + f;

    float a  = g_A[tid];
    float mn = CUDART_INF_F, mx = -CUDART_INF_F;

    #pragma unroll 8
    for (int i = 0; i < LL; i++) {
        float xv = p[(size_t)i * FF];
        a = fmaf(omw, a, w * xv);
        float u = xv * __powf(EPSC + a, -g);
        mn = fminf(mn, u);
        mx = fmaxf(mx, u);
    }

    #pragma unroll
    for (int o = 16; o; o >>= 1) {
        mn = fminf(mn, __shfl_xor_sync(0xFFFFFFFFu, mn, o));
        mx = fmaxf(mx, __shfl_xor_sync(0xFFFFFFFFu, mx, o));
    }
    __shared__ float smn[8], smx[8];
    int wid = threadIdx.x >> 5, lane = threadIdx.x & 31;
    if (lane == 0) { smn[wid] = mn; smx[wid] = mx; }
    __syncthreads();
    if (threadIdx.x == 0) {
        float bmn = smn[0], bmx = smx[0];
        #pragma unroll
        for (int i = 1; i < 8; i++) {
            bmn = fminf(bmn, smn[i]);
            bmx = fmaxf(bmx, smx[i]);
        }
        atomicMin(&g_minmax[0], f2key(bmn));
        atomicMax(&g_minmax[1], f2key(bmx));
    }
}

// ---------------------------------------------------------------------------
// K4: rescan, v' = (u+bias)^(1/r), normalize, write. bias^(1/r) cancels:
// out = (v' - v'min)*2/(v'max - v'min) - 1.
// vmn/vmx use the SAME formula as the loop body (incl. sqrt fast path for
// root==2), so the extreme elements map exactly to -1/+1.
// ---------------------------------------------------------------------------
__global__ void __launch_bounds__(256) k4_output(
    const float* __restrict__ x, float* __restrict__ out,
    const float* __restrict__ gain, const float* __restrict__ bias,
    const float* __restrict__ root, const float* __restrict__ smooth)
{
    int tid = blockIdx.x * blockDim.x + threadIdx.x;
    int f = tid & (FF - 1);
    int c = (tid >> 8) & (NCHUNK - 1);
    int b = tid >> 13;

    float w   = fminf(fmaxf(smooth[0], 0.0f), 1.0f);
    float omw = 1.0f - w;
    float g   = fminf(gain[0], 1.0f);
    float r   = fmaxf(root[0], 1.0f);
    float oor = 1.0f / r;
    float bs  = bias[0];
    bool  sq  = (oor == 0.5f);      // root == 2 -> exact sqrt fast path

    float umn = key2f(g_minmax[0]);
    float umx = key2f(g_minmax[1]);
    float vmn = sq ? sqrtf(umn + bs) : __powf(umn + bs, oor);
    float vmx = sq ? sqrtf(umx + bs) : __powf(umx + bs, oor);
    float sc  = 2.0f / (vmx - vmn);

    size_t off = ((size_t)(b * TT + c * LL)) * FF + f;
    const float* p = x + off;
    float*       q = out + off;

    float a = g_A[tid];

    #pragma unroll 8
    for (int i = 0; i < LL; i++) {
        float xv = p[(size_t)i * FF];
        a = fmaf(omw, a, w * xv);
        float u  = xv * __powf(EPSC + a, -g);
        float vp = sq ? sqrtf(u + bs) : __powf(u + bs, oor);
        q[(size_t)i * FF] = fmaf(vp - vmn, sc, -1.0f);
    }
}

extern "C" void kernel_launch(void* const* d_in, const int* in_sizes, int n_in,
                              void* d_out, int out_size)
{
    const float* x      = (const float*)d_in[0];
    const float* gain   = (const float*)d_in[1];
    const float* bias   = (const float*)d_in[2];
    const float* root   = (const float*)d_in[3];
    const float* smooth = (const float*)d_in[4];
    float* out = (float*)d_out;

    k1_chunk_scan<<<NTHREAD / 256, 256>>>(x, smooth);
    k2_combine<<<(NCHAIN + 255) / 256, 256>>>(x, smooth);
    k3_minmax<<<NTHREAD / 256, 256>>>(x, gain, smooth);
    k4_output<<<NTHREAD / 256, 256>>>(x, out, gain, bias, root, smooth);
}